// round 14
// baseline (speedup 1.0000x reference)
#include <cuda_runtime.h>
#include <cstdint>

typedef unsigned int u32;

// LSTM B=65536, T=20, I=36, H=30. Gate order i,f,g,o.
// Output: out[B,T,H] ++ h_n[1,B,H] ++ c_n[1,B,H], fp32.
//
// R13 skeleton (M=32/warp, D[120] live, ch-outer j-inner, 2 CTAs/SM) with:
//  - pure-x chunks (k 0..31): fp16 SINGLE-pass hi-only (A and B)
//  - x-tail/h chunks (k 32..63) + k8 (h tail + bias): fp16 2-pass A, B hi-only
//  - activations via tanh.approx.f32 (MUFU.TANH)
//  - out stores as float2 (15 iters instead of 30)

#define NB   65536
#define NT   20
#define NIn  36
#define NH   30

#define BLOCK 128                 // 4 warps, 128 batches per CTA
#define GRID  (NB / 128)          // 512

#define PITCH 72                  // x 0..35 | h 36..65 | bias(66)=1 | zeros
#define SLAB_FLOATS (32 * PITCH)  // 2304
#define SLAB_BYTES  (SLAB_FLOATS * 4)   // 9216
#define NTILE  15                 // N = 120 = 15 x 8, n = hh*4 + gate

// smem layout (bytes)
#define OFF_BF16 0                         // fp16 hi-only k16: 4ch*15j*32*uint2 = 15360
#define OFF_B8   15360                     // k8 fp16 hi-only: 15j*32*u32 = 1920
#define OFF_SLAB 17280
#define SMEM_BYTES (OFF_SLAB + 4 * SLAB_BYTES)   // 54144

// ---- fp16 helpers ----
__device__ __forceinline__ u32 f16x2_rn(float even, float odd) {
    u32 d;
    asm("cvt.rn.f16x2.f32 %0, %1, %2;" : "=r"(d) : "f"(odd), "f"(even));
    return d;
}
__device__ __forceinline__ void mk_ahl_f16(float2 f, u32& hi, u32& lo) {
    u32 h = f16x2_rn(f.x, f.y);
    float b0, b1;
    asm("{.reg .b16 l16, h16; mov.b32 {l16, h16}, %2;"
        " cvt.f32.f16 %0, l16; cvt.f32.f16 %1, h16;}"
        : "=f"(b0), "=f"(b1) : "r"(h));
    lo = f16x2_rn(f.x - b0, f.y - b1);
    hi = h;
}

// ---- MMA wrappers ----
__device__ __forceinline__ void mma_f16(float* d, u32 a0, u32 a1, u32 a2, u32 a3,
                                        u32 b0, u32 b1) {
    asm volatile(
        "mma.sync.aligned.m16n8k16.row.col.f32.f16.f16.f32 "
        "{%0,%1,%2,%3}, {%4,%5,%6,%7}, {%8,%9}, {%0,%1,%2,%3};"
        : "+f"(d[0]), "+f"(d[1]), "+f"(d[2]), "+f"(d[3])
        : "r"(a0), "r"(a1), "r"(a2), "r"(a3), "r"(b0), "r"(b1));
}
__device__ __forceinline__ void mma_k8_f16(float* d, u32 a0, u32 a1, u32 b0) {
    asm volatile(
        "mma.sync.aligned.m16n8k8.row.col.f32.f16.f16.f32 "
        "{%0,%1,%2,%3}, {%4,%5}, {%6}, {%0,%1,%2,%3};"
        : "+f"(d[0]), "+f"(d[1]), "+f"(d[2]), "+f"(d[3])
        : "r"(a0), "r"(a1), "r"(b0));
}

// ---- activations: MUFU.TANH based ----
__device__ __forceinline__ float tanh_ap(float v) {
    float y;
    asm("tanh.approx.f32 %0, %1;" : "=f"(y) : "f"(v));
    return y;
}
__device__ __forceinline__ float sigmoid_f(float v) {
    return fmaf(tanh_ap(0.5f * v), 0.5f, 0.5f);
}

__device__ __forceinline__ u32 s2u(const void* p) {
    u32 a;
    asm("{ .reg .u64 t; cvta.to.shared.u64 t, %1; cvt.u32.u64 %0, t; }"
        : "=r"(a) : "l"(p));
    return a;
}
#define CP16(dst, src) \
    asm volatile("cp.async.cg.shared.global [%0], [%1], 16;" :: "r"(dst), "l"(src))
#define CP_COMMIT() asm volatile("cp.async.commit_group;" ::: "memory")
#define CP_WAIT0()  asm volatile("cp.async.wait_group 0;" ::: "memory")

// concatenated weights: row n (gate-interleaved), col k in [0,72)
__device__ __forceinline__ float wcat(int n, int k,
                                      const float* W_ih, const float* W_hh,
                                      const float* b_ih, const float* b_hh) {
    int g = n & 3, hh = n >> 2;
    int row = g * NH + hh;
    if (k < 36) return W_ih[row * NIn + k];
    if (k < 66) return W_hh[row * NH + (k - 36)];
    if (k == 66) return b_ih[row] + b_hh[row];
    return 0.0f;
}

__global__ void __launch_bounds__(BLOCK, 2)
lstm_hmma_t14(const float* __restrict__ x,
              const float* __restrict__ W_ih,
              const float* __restrict__ W_hh,
              const float* __restrict__ b_ih,
              const float* __restrict__ b_hh,
              float* __restrict__ out) {
    extern __shared__ __align__(16) char smraw[];
    uint2* BsF = reinterpret_cast<uint2*>(smraw + OFF_BF16);   // k16 fp16 hi-only
    u32*   Bs8 = reinterpret_cast<u32*>(smraw + OFF_B8);       // k8 fp16 hi-only
    float* slab = reinterpret_cast<float*>(smraw + OFF_SLAB) + (threadIdx.x >> 5) * SLAB_FLOATS;

    const int tid  = threadIdx.x;
    const int lane = tid & 31;
    const int wB   = blockIdx.x * 128 + (tid >> 5) * 32;   // warp's first batch
    const u32 slab_u = s2u(slab);

    // ---- B tables (one-time) ----
    // fp16 hi-only k16 chunks: k = 0..63
    for (int idx = tid; idx < 4 * NTILE * 32; idx += BLOCK) {
        int ch  = idx / (NTILE * 32);
        int rem = idx - ch * NTILE * 32;
        int j   = rem >> 5, ln = rem & 31;
        int n   = j * 8 + (ln >> 2);
        int kb  = 16 * ch + 2 * (ln & 3);
        uint2 e;
        e.x = f16x2_rn(wcat(n, kb,     W_ih, W_hh, b_ih, b_hh),
                       wcat(n, kb + 1, W_ih, W_hh, b_ih, b_hh));
        e.y = f16x2_rn(wcat(n, kb + 8, W_ih, W_hh, b_ih, b_hh),
                       wcat(n, kb + 9, W_ih, W_hh, b_ih, b_hh));
        BsF[idx] = e;
    }
    // k8 chunk: k = 64..71 (h28, h29, bias col 66, zeros), fp16 hi-only
    for (int idx = tid; idx < NTILE * 32; idx += BLOCK) {
        int j = idx >> 5, ln = idx & 31;
        int n = j * 8 + (ln >> 2);
        int kb = 64 + 2 * (ln & 3);
        Bs8[idx] = f16x2_rn(wcat(n, kb,     W_ih, W_hh, b_ih, b_hh),
                            wcat(n, kb + 1, W_ih, W_hh, b_ih, b_hh));
    }

    // ---- per-warp slab init: zeros, bias column 66 = 1 ----
#pragma unroll
    for (int i = lane; i < SLAB_FLOATS / 4; i += 32)
        *reinterpret_cast<float4*>(slab + 4 * i) = make_float4(0, 0, 0, 0);
    __syncwarp();
    slab[lane * PITCH + 66] = 1.0f;     // one row per lane
    __syncthreads();

    // ---- prefetch x(t=0) via cp.async (cols 0..35 exactly) ----
#pragma unroll
    for (int k = 0; k < 9; k++) {
        int i = lane + 32 * k;          // 32 rows * 9 quads
        int rr = i / 9, q = i - rr * 9;
        CP16(slab_u + (rr * PITCH + 4 * q) * 4,
             x + (size_t)(wB + rr) * (NT * NIn) + 4 * q);
    }
    CP_COMMIT();

    const int r    = lane >> 2;               // frag row 0..7
    const bool ev  = (lane & 1) == 0;
    const int rowp = r + (ev ? 0 : 8);        // m0 cell row; m1 = rowp+16
    const int hsel = (lane >> 1) & 1;         // hh = 2j + hsel
    const int kofs = 2 * (lane & 3);

    float c0[NTILE], c1[NTILE];
#pragma unroll
    for (int j = 0; j < NTILE; j++) { c0[j] = 0.0f; c1[j] = 0.0f; }

    for (int t = 0; t < NT; t++) {
        CP_WAIT0();
        __syncwarp();                         // x(t) and h(t-1) visible

        float D[8 * NTILE];                   // m0: 0..59, m1: 60..119
#pragma unroll
        for (int i = 0; i < 8 * NTILE; i++) D[i] = 0.0f;

        // ---- pure-x chunks (k 0..31): fp16 single-pass hi-only ----
#pragma unroll
        for (int ch = 0; ch < 2; ch++) {
            int kb = 16 * ch + kofs;
            u32 A[8];
            A[0] = f16x2_rn(slab[r * PITCH + kb],            slab[r * PITCH + kb + 1]);
            A[1] = f16x2_rn(slab[(r + 8) * PITCH + kb],      slab[(r + 8) * PITCH + kb + 1]);
            A[2] = f16x2_rn(slab[r * PITCH + kb + 8],        slab[r * PITCH + kb + 9]);
            A[3] = f16x2_rn(slab[(r + 8) * PITCH + kb + 8],  slab[(r + 8) * PITCH + kb + 9]);
            A[4] = f16x2_rn(slab[(r + 16) * PITCH + kb],     slab[(r + 16) * PITCH + kb + 1]);
            A[5] = f16x2_rn(slab[(r + 24) * PITCH + kb],     slab[(r + 24) * PITCH + kb + 1]);
            A[6] = f16x2_rn(slab[(r + 16) * PITCH + kb + 8], slab[(r + 16) * PITCH + kb + 9]);
            A[7] = f16x2_rn(slab[(r + 24) * PITCH + kb + 8], slab[(r + 24) * PITCH + kb + 9]);
#pragma unroll
            for (int j = 0; j < NTILE; j++) {
                uint2 B = BsF[(ch * NTILE + j) * 32 + lane];
                mma_f16(D + 4 * j,      A[0], A[1], A[2], A[3], B.x, B.y);  // m0
                mma_f16(D + 60 + 4 * j, A[4], A[5], A[6], A[7], B.x, B.y);  // m1
            }
        }

        // ---- x-tail + h chunks (k 32..63): fp16 2-pass ----
#pragma unroll
        for (int ch = 2; ch < 4; ch++) {
            int kb = 16 * ch + kofs;
            u32 A[16];
            mk_ahl_f16(*reinterpret_cast<const float2*>(slab + r * PITCH + kb),            A[0], A[4]);
            mk_ahl_f16(*reinterpret_cast<const float2*>(slab + (r + 8) * PITCH + kb),      A[1], A[5]);
            mk_ahl_f16(*reinterpret_cast<const float2*>(slab + r * PITCH + kb + 8),        A[2], A[6]);
            mk_ahl_f16(*reinterpret_cast<const float2*>(slab + (r + 8) * PITCH + kb + 8),  A[3], A[7]);
            mk_ahl_f16(*reinterpret_cast<const float2*>(slab + (r + 16) * PITCH + kb),     A[8], A[12]);
            mk_ahl_f16(*reinterpret_cast<const float2*>(slab + (r + 24) * PITCH + kb),     A[9], A[13]);
            mk_ahl_f16(*reinterpret_cast<const float2*>(slab + (r + 16) * PITCH + kb + 8), A[10], A[14]);
            mk_ahl_f16(*reinterpret_cast<const float2*>(slab + (r + 24) * PITCH + kb + 8), A[11], A[15]);
#pragma unroll
            for (int j = 0; j < NTILE; j++) {
                uint2 B = BsF[(ch * NTILE + j) * 32 + lane];
                mma_f16(D + 4 * j,      A[0], A[1], A[2],  A[3],  B.x, B.y);  // m0 hi
                mma_f16(D + 60 + 4 * j, A[8], A[9], A[10], A[11], B.x, B.y);  // m1 hi
                mma_f16(D + 4 * j,      A[4], A[5], A[6],  A[7],  B.x, B.y);  // m0 lo
                mma_f16(D + 60 + 4 * j, A[12],A[13],A[14], A[15], B.x, B.y);  // m1 lo
            }
        }

        // ---- k8 chunk: k 64..71 (h tail + bias), fp16 2-pass ----
        {
            int kb = 64 + kofs;
            u32 A8[8];
            mk_ahl_f16(*reinterpret_cast<const float2*>(slab + r * PITCH + kb),        A8[0], A8[2]);
            mk_ahl_f16(*reinterpret_cast<const float2*>(slab + (r + 8) * PITCH + kb),  A8[1], A8[3]);
            mk_ahl_f16(*reinterpret_cast<const float2*>(slab + (r + 16) * PITCH + kb), A8[4], A8[6]);
            mk_ahl_f16(*reinterpret_cast<const float2*>(slab + (r + 24) * PITCH + kb), A8[5], A8[7]);
#pragma unroll
            for (int j = 0; j < NTILE; j++) {
                u32 B = Bs8[j * 32 + lane];
                mma_k8_f16(D + 4 * j,      A8[0], A8[1], B);   // m0 hi
                mma_k8_f16(D + 60 + 4 * j, A8[4], A8[5], B);   // m1 hi
                mma_k8_f16(D + 4 * j,      A8[2], A8[3], B);   // m0 lo
                mma_k8_f16(D + 60 + 4 * j, A8[6], A8[7], B);   // m1 lo
            }
        }

        // ---- all slab reads done: prefetch x(t+1) ----
        if (t < NT - 1) {
#pragma unroll
            for (int k = 0; k < 9; k++) {
                int i = lane + 32 * k;
                int rr = i / 9, q = i - rr * 9;
                CP16(slab_u + (rr * PITCH + 4 * q) * 4,
                     x + (size_t)(wB + rr) * (NT * NIn) + (t + 1) * NIn + 4 * q);
            }
            CP_COMMIT();
        }

        // ---- epilogue: 2 cells per lane per ntile; 2 shfls per (j,m) ----
#pragma unroll
        for (int j = 0; j < NTILE; j++) {
#pragma unroll
            for (int m = 0; m < 2; m++) {
                float* Dm = D + 60 * m + 4 * j;
                float d0 = Dm[0], d1 = Dm[1], d2 = Dm[2], d3 = Dm[3];
                // even lane sends d2/d3 (odd needs them), odd sends d0/d1
                float s0 = __shfl_xor_sync(0xffffffffu, ev ? d2 : d0, 1);
                float s1 = __shfl_xor_sync(0xffffffffu, ev ? d3 : d1, 1);
                float gi = ev ? d0 : s0;
                float gf = ev ? d1 : s1;
                float gg = ev ? s0 : d2;
                float go = ev ? s1 : d3;
                float it = sigmoid_f(gi), ft = sigmoid_f(gf);
                float gt = tanh_ap(gg),   ot = sigmoid_f(go);
                float* cr = m ? c1 : c0;
                float cn = fmaf(ft, cr[j], it * gt);
                cr[j] = cn;
                slab[(rowp + 16 * m) * PITCH + 36 + (2 * j + hsel)] = ot * tanh_ap(cn);
            }
        }
        __syncwarp();

        // ---- out write: 32 rows x 30 floats as 15 float2 per row ----
#pragma unroll
        for (int k = 0; k < 15; k++) {
            int i = lane + 32 * k;                  // < 480 = 32 rows * 15
            int rr = i / 15, cc = i - rr * 15;
            float2 v = *reinterpret_cast<const float2*>(slab + rr * PITCH + 36 + 2 * cc);
            *reinterpret_cast<float2*>(
                out + (size_t)(wB + rr) * (NT * NH) + t * NH + 2 * cc) = v;
        }
        __syncwarp();   // h reads done before next t's A-frag build
    }

    // ---- final states ----
    float* hN = out + (size_t)NB * NT * NH;
    float* cN = hN + (size_t)NB * NH;
#pragma unroll
    for (int k = 0; k < 15; k++) {
        int i = lane + 32 * k;
        int rr = i / 15, cc = i - rr * 15;
        float2 v = *reinterpret_cast<const float2*>(slab + rr * PITCH + 36 + 2 * cc);
        *reinterpret_cast<float2*>(hN + (size_t)(wB + rr) * NH + 2 * cc) = v;
    }
    __syncwarp();
#pragma unroll
    for (int j = 0; j < NTILE; j++) {
        slab[rowp * PITCH + 36 + (2 * j + hsel)]        = c0[j];
        slab[(rowp + 16) * PITCH + 36 + (2 * j + hsel)] = c1[j];
    }
    __syncwarp();
#pragma unroll
    for (int k = 0; k < 15; k++) {
        int i = lane + 32 * k;
        int rr = i / 15, cc = i - rr * 15;
        float2 v = *reinterpret_cast<const float2*>(slab + rr * PITCH + 36 + 2 * cc);
        *reinterpret_cast<float2*>(cN + (size_t)(wB + rr) * NH + 2 * cc) = v;
    }
}

extern "C" void kernel_launch(void* const* d_in, const int* in_sizes, int n_in,
                              void* d_out, int out_size) {
    const float* x    = (const float*)d_in[0];
    const float* W_ih = (const float*)d_in[1];
    const float* W_hh = (const float*)d_in[2];
    const float* b_ih = (const float*)d_in[3];
    const float* b_hh = (const float*)d_in[4];
    float* out = (float*)d_out;

    cudaFuncSetAttribute(lstm_hmma_t14,
                         cudaFuncAttributeMaxDynamicSharedMemorySize, SMEM_BYTES);
    lstm_hmma_t14<<<GRID, BLOCK, SMEM_BYTES>>>(x, W_ih, W_hh, b_ih, b_hh, out);
}

// round 15
// speedup vs baseline: 1.5437x; 1.5437x over previous
#include <cuda_runtime.h>
#include <cstdint>

typedef unsigned int u32;

// LSTM B=65536, T=20, I=36, H=30. Gate order i,f,g,o.
// Output: out[B,T,H] ++ h_n[1,B,H] ++ c_n[1,B,H], fp32.
//
// R13 champion skeleton, ONE change: pure-x chunks (k 0..31) use fp16
// SINGLE-pass hi-only with VECTORIZED float2 A-builds (A[8], fewer regs).
// Everything else identical to R13 (k8+h 2-pass, MUFU.TANH, scalar stores).

#define NB   65536
#define NT   20
#define NIn  36
#define NH   30

#define BLOCK 128                 // 4 warps, 128 batches per CTA
#define GRID  (NB / 128)          // 512

#define PITCH 72                  // x 0..35 | h 36..65 | bias(66)=1 | zeros
#define SLAB_FLOATS (32 * PITCH)  // 2304
#define SLAB_BYTES  (SLAB_FLOATS * 4)   // 9216
#define NTILE  15                 // N = 120 = 15 x 8, n = hh*4 + gate

// smem layout (bytes)
#define OFF_BF16 0                         // fp16 hi-only k16: 4ch*15j*32*uint2 = 15360
#define OFF_B8   15360                     // k8 fp16 hi-only: 15j*32*u32 = 1920
#define OFF_SLAB 17280
#define SMEM_BYTES (OFF_SLAB + 4 * SLAB_BYTES)   // 54144

// ---- fp16 helpers ----
__device__ __forceinline__ u32 f16x2_rn(float even, float odd) {
    u32 d;
    asm("cvt.rn.f16x2.f32 %0, %1, %2;" : "=r"(d) : "f"(odd), "f"(even));
    return d;
}
__device__ __forceinline__ void mk_ahl_f16(float2 f, u32& hi, u32& lo) {
    u32 h = f16x2_rn(f.x, f.y);
    float b0, b1;
    asm("{.reg .b16 l16, h16; mov.b32 {l16, h16}, %2;"
        " cvt.f32.f16 %0, l16; cvt.f32.f16 %1, h16;}"
        : "=f"(b0), "=f"(b1) : "r"(h));
    lo = f16x2_rn(f.x - b0, f.y - b1);
    hi = h;
}

// ---- MMA wrappers ----
__device__ __forceinline__ void mma_f16(float* d, u32 a0, u32 a1, u32 a2, u32 a3,
                                        u32 b0, u32 b1) {
    asm volatile(
        "mma.sync.aligned.m16n8k16.row.col.f32.f16.f16.f32 "
        "{%0,%1,%2,%3}, {%4,%5,%6,%7}, {%8,%9}, {%0,%1,%2,%3};"
        : "+f"(d[0]), "+f"(d[1]), "+f"(d[2]), "+f"(d[3])
        : "r"(a0), "r"(a1), "r"(a2), "r"(a3), "r"(b0), "r"(b1));
}
__device__ __forceinline__ void mma_k8_f16(float* d, u32 a0, u32 a1, u32 b0) {
    asm volatile(
        "mma.sync.aligned.m16n8k8.row.col.f32.f16.f16.f32 "
        "{%0,%1,%2,%3}, {%4,%5}, {%6}, {%0,%1,%2,%3};"
        : "+f"(d[0]), "+f"(d[1]), "+f"(d[2]), "+f"(d[3])
        : "r"(a0), "r"(a1), "r"(b0));
}

// ---- activations: MUFU.TANH based ----
__device__ __forceinline__ float tanh_ap(float v) {
    float y;
    asm("tanh.approx.f32 %0, %1;" : "=f"(y) : "f"(v));
    return y;
}
__device__ __forceinline__ float sigmoid_f(float v) {
    return fmaf(tanh_ap(0.5f * v), 0.5f, 0.5f);
}

__device__ __forceinline__ u32 s2u(const void* p) {
    u32 a;
    asm("{ .reg .u64 t; cvta.to.shared.u64 t, %1; cvt.u32.u64 %0, t; }"
        : "=r"(a) : "l"(p));
    return a;
}
#define CP16(dst, src) \
    asm volatile("cp.async.cg.shared.global [%0], [%1], 16;" :: "r"(dst), "l"(src))
#define CP_COMMIT() asm volatile("cp.async.commit_group;" ::: "memory")
#define CP_WAIT0()  asm volatile("cp.async.wait_group 0;" ::: "memory")

// concatenated weights: row n (gate-interleaved), col k in [0,72)
__device__ __forceinline__ float wcat(int n, int k,
                                      const float* W_ih, const float* W_hh,
                                      const float* b_ih, const float* b_hh) {
    int g = n & 3, hh = n >> 2;
    int row = g * NH + hh;
    if (k < 36) return W_ih[row * NIn + k];
    if (k < 66) return W_hh[row * NH + (k - 36)];
    if (k == 66) return b_ih[row] + b_hh[row];
    return 0.0f;
}

__global__ void __launch_bounds__(BLOCK, 2)
lstm_hmma_t15(const float* __restrict__ x,
              const float* __restrict__ W_ih,
              const float* __restrict__ W_hh,
              const float* __restrict__ b_ih,
              const float* __restrict__ b_hh,
              float* __restrict__ out) {
    extern __shared__ __align__(16) char smraw[];
    uint2* BsF = reinterpret_cast<uint2*>(smraw + OFF_BF16);   // k16 fp16 hi-only
    u32*   Bs8 = reinterpret_cast<u32*>(smraw + OFF_B8);       // k8 fp16 hi-only
    float* slab = reinterpret_cast<float*>(smraw + OFF_SLAB) + (threadIdx.x >> 5) * SLAB_FLOATS;

    const int tid  = threadIdx.x;
    const int lane = tid & 31;
    const int wB   = blockIdx.x * 128 + (tid >> 5) * 32;   // warp's first batch
    const u32 slab_u = s2u(slab);

    // ---- B tables (one-time) ----
    // fp16 hi-only k16 chunks: k = 0..63
    for (int idx = tid; idx < 4 * NTILE * 32; idx += BLOCK) {
        int ch  = idx / (NTILE * 32);
        int rem = idx - ch * NTILE * 32;
        int j   = rem >> 5, ln = rem & 31;
        int n   = j * 8 + (ln >> 2);
        int kb  = 16 * ch + 2 * (ln & 3);
        uint2 e;
        e.x = f16x2_rn(wcat(n, kb,     W_ih, W_hh, b_ih, b_hh),
                       wcat(n, kb + 1, W_ih, W_hh, b_ih, b_hh));
        e.y = f16x2_rn(wcat(n, kb + 8, W_ih, W_hh, b_ih, b_hh),
                       wcat(n, kb + 9, W_ih, W_hh, b_ih, b_hh));
        BsF[idx] = e;
    }
    // k8 chunk: k = 64..71 (h28, h29, bias col 66, zeros), fp16 hi-only
    for (int idx = tid; idx < NTILE * 32; idx += BLOCK) {
        int j = idx >> 5, ln = idx & 31;
        int n = j * 8 + (ln >> 2);
        int kb = 64 + 2 * (ln & 3);
        Bs8[idx] = f16x2_rn(wcat(n, kb,     W_ih, W_hh, b_ih, b_hh),
                            wcat(n, kb + 1, W_ih, W_hh, b_ih, b_hh));
    }

    // ---- per-warp slab init: zeros, bias column 66 = 1 ----
#pragma unroll
    for (int i = lane; i < SLAB_FLOATS / 4; i += 32)
        *reinterpret_cast<float4*>(slab + 4 * i) = make_float4(0, 0, 0, 0);
    __syncwarp();
    slab[lane * PITCH + 66] = 1.0f;     // one row per lane
    __syncthreads();

    // ---- prefetch x(t=0) via cp.async (cols 0..35 exactly) ----
#pragma unroll
    for (int k = 0; k < 9; k++) {
        int i = lane + 32 * k;          // 32 rows * 9 quads
        int rr = i / 9, q = i - rr * 9;
        CP16(slab_u + (rr * PITCH + 4 * q) * 4,
             x + (size_t)(wB + rr) * (NT * NIn) + 4 * q);
    }
    CP_COMMIT();

    const int r    = lane >> 2;               // frag row 0..7
    const bool ev  = (lane & 1) == 0;
    const int rowp = r + (ev ? 0 : 8);        // m0 cell row; m1 = rowp+16
    const int hsel = (lane >> 1) & 1;         // hh = 2j + hsel
    const int kofs = 2 * (lane & 3);

    float c0[NTILE], c1[NTILE];
#pragma unroll
    for (int j = 0; j < NTILE; j++) { c0[j] = 0.0f; c1[j] = 0.0f; }

    for (int t = 0; t < NT; t++) {
        CP_WAIT0();
        __syncwarp();                         // x(t) and h(t-1) visible

        float D[8 * NTILE];                   // m0: 0..59, m1: 60..119
#pragma unroll
        for (int i = 0; i < 8 * NTILE; i++) D[i] = 0.0f;

        // ---- pure-x chunks (k 0..31): fp16 single-pass, float2 A-builds ----
#pragma unroll
        for (int ch = 0; ch < 2; ch++) {
            int kb = 16 * ch + kofs;
            u32 A[8];
            {
                float2 f;
                f = *reinterpret_cast<const float2*>(slab + r * PITCH + kb);            A[0] = f16x2_rn(f.x, f.y);
                f = *reinterpret_cast<const float2*>(slab + (r + 8) * PITCH + kb);      A[1] = f16x2_rn(f.x, f.y);
                f = *reinterpret_cast<const float2*>(slab + r * PITCH + kb + 8);        A[2] = f16x2_rn(f.x, f.y);
                f = *reinterpret_cast<const float2*>(slab + (r + 8) * PITCH + kb + 8);  A[3] = f16x2_rn(f.x, f.y);
                f = *reinterpret_cast<const float2*>(slab + (r + 16) * PITCH + kb);     A[4] = f16x2_rn(f.x, f.y);
                f = *reinterpret_cast<const float2*>(slab + (r + 24) * PITCH + kb);     A[5] = f16x2_rn(f.x, f.y);
                f = *reinterpret_cast<const float2*>(slab + (r + 16) * PITCH + kb + 8); A[6] = f16x2_rn(f.x, f.y);
                f = *reinterpret_cast<const float2*>(slab + (r + 24) * PITCH + kb + 8); A[7] = f16x2_rn(f.x, f.y);
            }
#pragma unroll
            for (int j = 0; j < NTILE; j++) {
                uint2 B = BsF[(ch * NTILE + j) * 32 + lane];
                mma_f16(D + 4 * j,      A[0], A[1], A[2], A[3], B.x, B.y);  // m0
                mma_f16(D + 60 + 4 * j, A[4], A[5], A[6], A[7], B.x, B.y);  // m1
            }
        }

        // ---- x-tail + h chunks (k 32..63): fp16 2-pass ----
#pragma unroll
        for (int ch = 2; ch < 4; ch++) {
            int kb = 16 * ch + kofs;
            u32 A[16];
            mk_ahl_f16(*reinterpret_cast<const float2*>(slab + r * PITCH + kb),            A[0], A[4]);
            mk_ahl_f16(*reinterpret_cast<const float2*>(slab + (r + 8) * PITCH + kb),      A[1], A[5]);
            mk_ahl_f16(*reinterpret_cast<const float2*>(slab + r * PITCH + kb + 8),        A[2], A[6]);
            mk_ahl_f16(*reinterpret_cast<const float2*>(slab + (r + 8) * PITCH + kb + 8),  A[3], A[7]);
            mk_ahl_f16(*reinterpret_cast<const float2*>(slab + (r + 16) * PITCH + kb),     A[8], A[12]);
            mk_ahl_f16(*reinterpret_cast<const float2*>(slab + (r + 24) * PITCH + kb),     A[9], A[13]);
            mk_ahl_f16(*reinterpret_cast<const float2*>(slab + (r + 16) * PITCH + kb + 8), A[10], A[14]);
            mk_ahl_f16(*reinterpret_cast<const float2*>(slab + (r + 24) * PITCH + kb + 8), A[11], A[15]);
#pragma unroll
            for (int j = 0; j < NTILE; j++) {
                uint2 B = BsF[(ch * NTILE + j) * 32 + lane];
                mma_f16(D + 4 * j,      A[0], A[1], A[2],  A[3],  B.x, B.y);  // m0 hi
                mma_f16(D + 60 + 4 * j, A[8], A[9], A[10], A[11], B.x, B.y);  // m1 hi
                mma_f16(D + 4 * j,      A[4], A[5], A[6],  A[7],  B.x, B.y);  // m0 lo
                mma_f16(D + 60 + 4 * j, A[12],A[13],A[14], A[15], B.x, B.y);  // m1 lo
            }
        }

        // ---- k8 chunk: k 64..71 (h tail + bias), fp16 2-pass ----
        {
            int kb = 64 + kofs;
            u32 A8[8];
            mk_ahl_f16(*reinterpret_cast<const float2*>(slab + r * PITCH + kb),        A8[0], A8[2]);
            mk_ahl_f16(*reinterpret_cast<const float2*>(slab + (r + 8) * PITCH + kb),  A8[1], A8[3]);
            mk_ahl_f16(*reinterpret_cast<const float2*>(slab + (r + 16) * PITCH + kb), A8[4], A8[6]);
            mk_ahl_f16(*reinterpret_cast<const float2*>(slab + (r + 24) * PITCH + kb), A8[5], A8[7]);
#pragma unroll
            for (int j = 0; j < NTILE; j++) {
                u32 B = Bs8[j * 32 + lane];
                mma_k8_f16(D + 4 * j,      A8[0], A8[1], B);   // m0 hi
                mma_k8_f16(D + 60 + 4 * j, A8[4], A8[5], B);   // m1 hi
                mma_k8_f16(D + 4 * j,      A8[2], A8[3], B);   // m0 lo
                mma_k8_f16(D + 60 + 4 * j, A8[6], A8[7], B);   // m1 lo
            }
        }

        // ---- all slab reads done: prefetch x(t+1) ----
        if (t < NT - 1) {
#pragma unroll
            for (int k = 0; k < 9; k++) {
                int i = lane + 32 * k;
                int rr = i / 9, q = i - rr * 9;
                CP16(slab_u + (rr * PITCH + 4 * q) * 4,
                     x + (size_t)(wB + rr) * (NT * NIn) + (t + 1) * NIn + 4 * q);
            }
            CP_COMMIT();
        }

        // ---- epilogue: 2 cells per lane per ntile; 2 shfls per (j,m) ----
#pragma unroll
        for (int j = 0; j < NTILE; j++) {
#pragma unroll
            for (int m = 0; m < 2; m++) {
                float* Dm = D + 60 * m + 4 * j;
                float d0 = Dm[0], d1 = Dm[1], d2 = Dm[2], d3 = Dm[3];
                // even lane sends d2/d3 (odd needs them), odd sends d0/d1
                float s0 = __shfl_xor_sync(0xffffffffu, ev ? d2 : d0, 1);
                float s1 = __shfl_xor_sync(0xffffffffu, ev ? d3 : d1, 1);
                float gi = ev ? d0 : s0;
                float gf = ev ? d1 : s1;
                float gg = ev ? s0 : d2;
                float go = ev ? s1 : d3;
                float it = sigmoid_f(gi), ft = sigmoid_f(gf);
                float gt = tanh_ap(gg),   ot = sigmoid_f(go);
                float* cr = m ? c1 : c0;
                float cn = fmaf(ft, cr[j], it * gt);
                cr[j] = cn;
                slab[(rowp + 16 * m) * PITCH + 36 + (2 * j + hsel)] = ot * tanh_ap(cn);
            }
        }
        __syncwarp();

        // ---- out write: 32 rows x 30 from slab h cols (R13 pattern) ----
#pragma unroll
        for (int k = 0; k < 30; k++) {
            int i = lane + 32 * k;                  // < 960
            int rr = i / 30, cc = i - rr * 30;
            out[(size_t)(wB + rr) * (NT * NH) + t * NH + cc] =
                slab[rr * PITCH + 36 + cc];
        }
        __syncwarp();   // h reads done before next t's A-frag build
    }

    // ---- final states ----
    float* hN = out + (size_t)NB * NT * NH;
    float* cN = hN + (size_t)NB * NH;
#pragma unroll
    for (int k = 0; k < 30; k++) {
        int i = lane + 32 * k;
        int rr = i / 30, cc = i - rr * 30;
        hN[(size_t)(wB + rr) * NH + cc] = slab[rr * PITCH + 36 + cc];
    }
    __syncwarp();
#pragma unroll
    for (int j = 0; j < NTILE; j++) {
        slab[rowp * PITCH + 36 + (2 * j + hsel)]        = c0[j];
        slab[(rowp + 16) * PITCH + 36 + (2 * j + hsel)] = c1[j];
    }
    __syncwarp();
#pragma unroll
    for (int k = 0; k < 30; k++) {
        int i = lane + 32 * k;
        int rr = i / 30, cc = i - rr * 30;
        cN[(size_t)(wB + rr) * NH + cc] = slab[rr * PITCH + 36 + cc];
    }
}

extern "C" void kernel_launch(void* const* d_in, const int* in_sizes, int n_in,
                              void* d_out, int out_size) {
    const float* x    = (const float*)d_in[0];
    const float* W_ih = (const float*)d_in[1];
    const float* W_hh = (const float*)d_in[2];
    const float* b_ih = (const float*)d_in[3];
    const float* b_hh = (const float*)d_in[4];
    float* out = (float*)d_out;

    cudaFuncSetAttribute(lstm_hmma_t15,
                         cudaFuncAttributeMaxDynamicSharedMemorySize, SMEM_BYTES);
    lstm_hmma_t15<<<GRID, BLOCK, SMEM_BYTES>>>(x, W_ih, W_hh, b_ih, b_hh, out);
}

// round 16
// speedup vs baseline: 1.7345x; 1.1237x over previous
#include <cuda_runtime.h>
#include <cstdint>

typedef unsigned int u32;

// LSTM B=65536, T=20, I=36, H=30. Gate order i,f,g,o.
// Output: out[B,T,H] ++ h_n[1,B,H] ++ c_n[1,B,H], fp32.
//
// R15 skeleton, ONE change: ALL chunks fp16 SINGLE-pass hi-only
// (A-lo compensation dropped on h chunks + k8 as well).
// 150 MMAs/warp-t (was 240). Everything else identical to R15.

#define NB   65536
#define NT   20
#define NIn  36
#define NH   30

#define BLOCK 128                 // 4 warps, 128 batches per CTA
#define GRID  (NB / 128)          // 512

#define PITCH 72                  // x 0..35 | h 36..65 | bias(66)=1 | zeros
#define SLAB_FLOATS (32 * PITCH)  // 2304
#define SLAB_BYTES  (SLAB_FLOATS * 4)   // 9216
#define NTILE  15                 // N = 120 = 15 x 8, n = hh*4 + gate

// smem layout (bytes)
#define OFF_BF16 0                         // fp16 hi-only k16: 4ch*15j*32*uint2 = 15360
#define OFF_B8   15360                     // k8 fp16 hi-only: 15j*32*u32 = 1920
#define OFF_SLAB 17280
#define SMEM_BYTES (OFF_SLAB + 4 * SLAB_BYTES)   // 54144

// ---- fp16 helpers ----
__device__ __forceinline__ u32 f16x2_rn(float even, float odd) {
    u32 d;
    asm("cvt.rn.f16x2.f32 %0, %1, %2;" : "=r"(d) : "f"(odd), "f"(even));
    return d;
}

// ---- MMA wrappers ----
__device__ __forceinline__ void mma_f16(float* d, u32 a0, u32 a1, u32 a2, u32 a3,
                                        u32 b0, u32 b1) {
    asm volatile(
        "mma.sync.aligned.m16n8k16.row.col.f32.f16.f16.f32 "
        "{%0,%1,%2,%3}, {%4,%5,%6,%7}, {%8,%9}, {%0,%1,%2,%3};"
        : "+f"(d[0]), "+f"(d[1]), "+f"(d[2]), "+f"(d[3])
        : "r"(a0), "r"(a1), "r"(a2), "r"(a3), "r"(b0), "r"(b1));
}
__device__ __forceinline__ void mma_k8_f16(float* d, u32 a0, u32 a1, u32 b0) {
    asm volatile(
        "mma.sync.aligned.m16n8k8.row.col.f32.f16.f16.f32 "
        "{%0,%1,%2,%3}, {%4,%5}, {%6}, {%0,%1,%2,%3};"
        : "+f"(d[0]), "+f"(d[1]), "+f"(d[2]), "+f"(d[3])
        : "r"(a0), "r"(a1), "r"(b0));
}

// ---- activations: MUFU.TANH based ----
__device__ __forceinline__ float tanh_ap(float v) {
    float y;
    asm("tanh.approx.f32 %0, %1;" : "=f"(y) : "f"(v));
    return y;
}
__device__ __forceinline__ float sigmoid_f(float v) {
    return fmaf(tanh_ap(0.5f * v), 0.5f, 0.5f);
}

__device__ __forceinline__ u32 s2u(const void* p) {
    u32 a;
    asm("{ .reg .u64 t; cvta.to.shared.u64 t, %1; cvt.u32.u64 %0, t; }"
        : "=r"(a) : "l"(p));
    return a;
}
#define CP16(dst, src) \
    asm volatile("cp.async.cg.shared.global [%0], [%1], 16;" :: "r"(dst), "l"(src))
#define CP_COMMIT() asm volatile("cp.async.commit_group;" ::: "memory")
#define CP_WAIT0()  asm volatile("cp.async.wait_group 0;" ::: "memory")

// concatenated weights: row n (gate-interleaved), col k in [0,72)
__device__ __forceinline__ float wcat(int n, int k,
                                      const float* W_ih, const float* W_hh,
                                      const float* b_ih, const float* b_hh) {
    int g = n & 3, hh = n >> 2;
    int row = g * NH + hh;
    if (k < 36) return W_ih[row * NIn + k];
    if (k < 66) return W_hh[row * NH + (k - 36)];
    if (k == 66) return b_ih[row] + b_hh[row];
    return 0.0f;
}

__global__ void __launch_bounds__(BLOCK, 2)
lstm_hmma_t16(const float* __restrict__ x,
              const float* __restrict__ W_ih,
              const float* __restrict__ W_hh,
              const float* __restrict__ b_ih,
              const float* __restrict__ b_hh,
              float* __restrict__ out) {
    extern __shared__ __align__(16) char smraw[];
    uint2* BsF = reinterpret_cast<uint2*>(smraw + OFF_BF16);   // k16 fp16 hi-only
    u32*   Bs8 = reinterpret_cast<u32*>(smraw + OFF_B8);       // k8 fp16 hi-only
    float* slab = reinterpret_cast<float*>(smraw + OFF_SLAB) + (threadIdx.x >> 5) * SLAB_FLOATS;

    const int tid  = threadIdx.x;
    const int lane = tid & 31;
    const int wB   = blockIdx.x * 128 + (tid >> 5) * 32;   // warp's first batch
    const u32 slab_u = s2u(slab);

    // ---- B tables (one-time) ----
    // fp16 hi-only k16 chunks: k = 0..63
    for (int idx = tid; idx < 4 * NTILE * 32; idx += BLOCK) {
        int ch  = idx / (NTILE * 32);
        int rem = idx - ch * NTILE * 32;
        int j   = rem >> 5, ln = rem & 31;
        int n   = j * 8 + (ln >> 2);
        int kb  = 16 * ch + 2 * (ln & 3);
        uint2 e;
        e.x = f16x2_rn(wcat(n, kb,     W_ih, W_hh, b_ih, b_hh),
                       wcat(n, kb + 1, W_ih, W_hh, b_ih, b_hh));
        e.y = f16x2_rn(wcat(n, kb + 8, W_ih, W_hh, b_ih, b_hh),
                       wcat(n, kb + 9, W_ih, W_hh, b_ih, b_hh));
        BsF[idx] = e;
    }
    // k8 chunk: k = 64..71 (h28, h29, bias col 66, zeros), fp16 hi-only
    for (int idx = tid; idx < NTILE * 32; idx += BLOCK) {
        int j = idx >> 5, ln = idx & 31;
        int n = j * 8 + (ln >> 2);
        int kb = 64 + 2 * (ln & 3);
        Bs8[idx] = f16x2_rn(wcat(n, kb,     W_ih, W_hh, b_ih, b_hh),
                            wcat(n, kb + 1, W_ih, W_hh, b_ih, b_hh));
    }

    // ---- per-warp slab init: zeros, bias column 66 = 1 ----
#pragma unroll
    for (int i = lane; i < SLAB_FLOATS / 4; i += 32)
        *reinterpret_cast<float4*>(slab + 4 * i) = make_float4(0, 0, 0, 0);
    __syncwarp();
    slab[lane * PITCH + 66] = 1.0f;     // one row per lane
    __syncthreads();

    // ---- prefetch x(t=0) via cp.async (cols 0..35 exactly) ----
#pragma unroll
    for (int k = 0; k < 9; k++) {
        int i = lane + 32 * k;          // 32 rows * 9 quads
        int rr = i / 9, q = i - rr * 9;
        CP16(slab_u + (rr * PITCH + 4 * q) * 4,
             x + (size_t)(wB + rr) * (NT * NIn) + 4 * q);
    }
    CP_COMMIT();

    const int r    = lane >> 2;               // frag row 0..7
    const bool ev  = (lane & 1) == 0;
    const int rowp = r + (ev ? 0 : 8);        // m0 cell row; m1 = rowp+16
    const int hsel = (lane >> 1) & 1;         // hh = 2j + hsel
    const int kofs = 2 * (lane & 3);

    float c0[NTILE], c1[NTILE];
#pragma unroll
    for (int j = 0; j < NTILE; j++) { c0[j] = 0.0f; c1[j] = 0.0f; }

    for (int t = 0; t < NT; t++) {
        CP_WAIT0();
        __syncwarp();                         // x(t) and h(t-1) visible

        float D[8 * NTILE];                   // m0: 0..59, m1: 60..119
#pragma unroll
        for (int i = 0; i < 8 * NTILE; i++) D[i] = 0.0f;

        // ---- k16 chunks (k 0..63): fp16 single-pass, float2 A-builds ----
#pragma unroll
        for (int ch = 0; ch < 4; ch++) {
            int kb = 16 * ch + kofs;
            u32 A[8];
            {
                float2 f;
                f = *reinterpret_cast<const float2*>(slab + r * PITCH + kb);            A[0] = f16x2_rn(f.x, f.y);
                f = *reinterpret_cast<const float2*>(slab + (r + 8) * PITCH + kb);      A[1] = f16x2_rn(f.x, f.y);
                f = *reinterpret_cast<const float2*>(slab + r * PITCH + kb + 8);        A[2] = f16x2_rn(f.x, f.y);
                f = *reinterpret_cast<const float2*>(slab + (r + 8) * PITCH + kb + 8);  A[3] = f16x2_rn(f.x, f.y);
                f = *reinterpret_cast<const float2*>(slab + (r + 16) * PITCH + kb);     A[4] = f16x2_rn(f.x, f.y);
                f = *reinterpret_cast<const float2*>(slab + (r + 24) * PITCH + kb);     A[5] = f16x2_rn(f.x, f.y);
                f = *reinterpret_cast<const float2*>(slab + (r + 16) * PITCH + kb + 8); A[6] = f16x2_rn(f.x, f.y);
                f = *reinterpret_cast<const float2*>(slab + (r + 24) * PITCH + kb + 8); A[7] = f16x2_rn(f.x, f.y);
            }
#pragma unroll
            for (int j = 0; j < NTILE; j++) {
                uint2 B = BsF[(ch * NTILE + j) * 32 + lane];
                mma_f16(D + 4 * j,      A[0], A[1], A[2], A[3], B.x, B.y);  // m0
                mma_f16(D + 60 + 4 * j, A[4], A[5], A[6], A[7], B.x, B.y);  // m1
            }
        }

        // ---- k8 chunk: k 64..71 (h tail + bias), fp16 single-pass ----
        {
            int kb = 64 + kofs;
            u32 A8[4];
            {
                float2 f;
                f = *reinterpret_cast<const float2*>(slab + r * PITCH + kb);        A8[0] = f16x2_rn(f.x, f.y);
                f = *reinterpret_cast<const float2*>(slab + (r + 8) * PITCH + kb);  A8[1] = f16x2_rn(f.x, f.y);
                f = *reinterpret_cast<const float2*>(slab + (r + 16) * PITCH + kb); A8[2] = f16x2_rn(f.x, f.y);
                f = *reinterpret_cast<const float2*>(slab + (r + 24) * PITCH + kb); A8[3] = f16x2_rn(f.x, f.y);
            }
#pragma unroll
            for (int j = 0; j < NTILE; j++) {
                u32 B = Bs8[j * 32 + lane];
                mma_k8_f16(D + 4 * j,      A8[0], A8[1], B);   // m0
                mma_k8_f16(D + 60 + 4 * j, A8[2], A8[3], B);   // m1
            }
        }

        // ---- all slab reads done: prefetch x(t+1) ----
        if (t < NT - 1) {
#pragma unroll
            for (int k = 0; k < 9; k++) {
                int i = lane + 32 * k;
                int rr = i / 9, q = i - rr * 9;
                CP16(slab_u + (rr * PITCH + 4 * q) * 4,
                     x + (size_t)(wB + rr) * (NT * NIn) + (t + 1) * NIn + 4 * q);
            }
            CP_COMMIT();
        }

        // ---- epilogue: 2 cells per lane per ntile; 2 shfls per (j,m) ----
#pragma unroll
        for (int j = 0; j < NTILE; j++) {
#pragma unroll
            for (int m = 0; m < 2; m++) {
                float* Dm = D + 60 * m + 4 * j;
                float d0 = Dm[0], d1 = Dm[1], d2 = Dm[2], d3 = Dm[3];
                // even lane sends d2/d3 (odd needs them), odd sends d0/d1
                float s0 = __shfl_xor_sync(0xffffffffu, ev ? d2 : d0, 1);
                float s1 = __shfl_xor_sync(0xffffffffu, ev ? d3 : d1, 1);
                float gi = ev ? d0 : s0;
                float gf = ev ? d1 : s1;
                float gg = ev ? s0 : d2;
                float go = ev ? s1 : d3;
                float it = sigmoid_f(gi), ft = sigmoid_f(gf);
                float gt = tanh_ap(gg),   ot = sigmoid_f(go);
                float* cr = m ? c1 : c0;
                float cn = fmaf(ft, cr[j], it * gt);
                cr[j] = cn;
                slab[(rowp + 16 * m) * PITCH + 36 + (2 * j + hsel)] = ot * tanh_ap(cn);
            }
        }
        __syncwarp();

        // ---- out write: 32 rows x 30 from slab h cols ----
#pragma unroll
        for (int k = 0; k < 30; k++) {
            int i = lane + 32 * k;                  // < 960
            int rr = i / 30, cc = i - rr * 30;
            out[(size_t)(wB + rr) * (NT * NH) + t * NH + cc] =
                slab[rr * PITCH + 36 + cc];
        }
        __syncwarp();   // h reads done before next t's A-frag build
    }

    // ---- final states ----
    float* hN = out + (size_t)NB * NT * NH;
    float* cN = hN + (size_t)NB * NH;
#pragma unroll
    for (int k = 0; k < 30; k++) {
        int i = lane + 32 * k;
        int rr = i / 30, cc = i - rr * 30;
        hN[(size_t)(wB + rr) * NH + cc] = slab[rr * PITCH + 36 + cc];
    }
    __syncwarp();
#pragma unroll
    for (int j = 0; j < NTILE; j++) {
        slab[rowp * PITCH + 36 + (2 * j + hsel)]        = c0[j];
        slab[(rowp + 16) * PITCH + 36 + (2 * j + hsel)] = c1[j];
    }
    __syncwarp();
#pragma unroll
    for (int k = 0; k < 30; k++) {
        int i = lane + 32 * k;
        int rr = i / 30, cc = i - rr * 30;
        cN[(size_t)(wB + rr) * NH + cc] = slab[rr * PITCH + 36 + cc];
    }
}

extern "C" void kernel_launch(void* const* d_in, const int* in_sizes, int n_in,
                              void* d_out, int out_size) {
    const float* x    = (const float*)d_in[0];
    const float* W_ih = (const float*)d_in[1];
    const float* W_hh = (const float*)d_in[2];
    const float* b_ih = (const float*)d_in[3];
    const float* b_hh = (const float*)d_in[4];
    float* out = (float*)d_out;

    cudaFuncSetAttribute(lstm_hmma_t16,
                         cudaFuncAttributeMaxDynamicSharedMemorySize, SMEM_BYTES);
    lstm_hmma_t16<<<GRID, BLOCK, SMEM_BYTES>>>(x, W_ih, W_hh, b_ih, b_hh, out);
}